// round 4
// baseline (speedup 1.0000x reference)
#include <cuda_runtime.h>
#include <cstdint>

#define NTOT 32768
#define FDIM 128
#define EMBD 32
#define NG   32
#define NPG  1024
#define OFF_SRC 1048576u
#define OFF_DST 34603008u
#define OFF_EW  68157440u

__device__ float g_xgT[NG * EMBD * NPG];   // [g][k][i]
__device__ float g_sq[NTOT];
__device__ float g_stats[33];              // [0..31]=centroid, [32]=scale

// ---------------------------------------------------------------------------
__device__ __forceinline__ void unpack2(unsigned long long v, float& lo, float& hi) {
    asm("mov.b64 {%0, %1}, %2;" : "=f"(lo), "=f"(hi) : "l"(v));
}
__device__ __forceinline__ unsigned long long ffma2(unsigned long long a,
                                                    unsigned long long b,
                                                    unsigned long long c) {
    unsigned long long d;
    asm("fma.rn.f32x2 %0, %1, %2, %3;" : "=l"(d) : "l"(a), "l"(b), "l"(c));
    return d;
}
__device__ __forceinline__ void st_cs(float* p, float4 v) {
    asm volatile("st.global.cs.v4.f32 [%0], {%1,%2,%3,%4};"
                 :: "l"(p), "f"(v.x), "f"(v.y), "f"(v.z), "f"(v.w) : "memory");
}

// ---------------------------------------------------------------------------
// K1: xe = x @ W  (32768x128 @ 128x32)
// ---------------------------------------------------------------------------
__global__ __launch_bounds__(256) void k1_gemm(const float* __restrict__ x,
                                               const float* __restrict__ W,
                                               float* __restrict__ xe) {
    __shared__ float ws[FDIM * EMBD];
    __shared__ float xs[32 * FDIM];
    const int t = threadIdx.x;
    const int row0 = blockIdx.x * 32;

    for (int e = t; e < FDIM * EMBD; e += 256) ws[e] = W[e];
    for (int e = t; e < 1024; e += 256)
        ((float4*)xs)[e] = ((const float4*)(x + (size_t)row0 * FDIM))[e];
    __syncthreads();

    const int r  = t >> 3;
    const int d0 = (t & 7) * 4;
    float a0 = 0.f, a1 = 0.f, a2 = 0.f, a3 = 0.f;
#pragma unroll
    for (int k = 0; k < FDIM; k++) {
        const float xv = xs[r * FDIM + k];
        const float4 w4 = *(const float4*)&ws[k * EMBD + d0];
        a0 = fmaf(xv, w4.x, a0);
        a1 = fmaf(xv, w4.y, a1);
        a2 = fmaf(xv, w4.z, a2);
        a3 = fmaf(xv, w4.w, a3);
    }
    *(float4*)&xe[(size_t)(row0 + r) * EMBD + d0] = make_float4(a0, a1, a2, a3);
}

// ---------------------------------------------------------------------------
// K2: centroid + scale. 1024 threads, rows held in registers across passes.
// ---------------------------------------------------------------------------
__global__ __launch_bounds__(1024) void k2_stats(const float* __restrict__ xe) {
    __shared__ float part[32 * 32];
    __shared__ float cent[EMBD];
    const int t = threadIdx.x;
    const int w = t >> 5, l = t & 31;

    float v[EMBD];
#pragma unroll
    for (int q = 0; q < 8; q++) {
        const float4 f = ((const float4*)(xe + (size_t)t * EMBD))[q];
        v[4 * q] = f.x; v[4 * q + 1] = f.y; v[4 * q + 2] = f.z; v[4 * q + 3] = f.w;
    }
#pragma unroll
    for (int d = 0; d < EMBD; d++) {
        float s = v[d];
#pragma unroll
        for (int o = 16; o; o >>= 1) s += __shfl_xor_sync(0xffffffffu, s, o);
        if (l == 0) part[w * 32 + d] = s;
    }
    __syncthreads();
    if (w == 0) {
        float s = 0.f;
#pragma unroll
        for (int b = 0; b < 32; b++) s += part[b * 32 + l];
        const float c = s * (1.0f / 1024.0f);
        cent[l] = c;
        g_stats[l] = c;
    }
    __syncthreads();
#pragma unroll
    for (int d = 0; d < EMBD; d++) {
        float m = fabsf(v[d] - cent[d]);
#pragma unroll
        for (int o = 16; o; o >>= 1) m = fmaxf(m, __shfl_xor_sync(0xffffffffu, m, o));
        if (l == 0) part[w * 32 + d] = m;
    }
    __syncthreads();
    if (w == 0) {
        float m = 0.f;
#pragma unroll
        for (int b = 0; b < 32; b++) m = fmaxf(m, part[b * 32 + l]);
#pragma unroll
        for (int o = 16; o; o >>= 1) m = fmaxf(m, __shfl_xor_sync(0xffffffffu, m, o));
        if (l == 0) g_stats[32] = 0.9f / m;
    }
}

// ---------------------------------------------------------------------------
// K3: normalize -> transposed per-graph layout + row norms
// ---------------------------------------------------------------------------
__global__ __launch_bounds__(256) void k3_norm(const float* __restrict__ xe) {
    const int i = blockIdx.x * 256 + threadIdx.x;
    const float scale = g_stats[32];
    const int g  = i >> 10;
    const int il = i & 1023;
    const float* row = xe + (size_t)i * EMBD;
    float* dstb = g_xgT + (size_t)g * (EMBD * NPG) + il;
    float s = 0.f;
#pragma unroll
    for (int k = 0; k < EMBD; k++) {
        const float v = (row[k] - g_stats[k]) * scale;
        dstb[k * NPG] = v;
        s = fmaf(v, v, s);
    }
    g_sq[i] = s;
}

// ---------------------------------------------------------------------------
// K4: 128x64 tiles, 256 threads, 8x4/thread.
//  - src/dst (268 MB, index-only) stored FIRST -> overlap with FMA mainloop.
//  - i-tile stored duplicated (v,v) in smem: A operand = direct LDS.128,
//    B pair = direct LDS of in-memory float pair. Zero pack movs in loop.
// ---------------------------------------------------------------------------
__global__ __launch_bounds__(256, 4) void k4_pair(float* __restrict__ out,
                                                  const float* __restrict__ tptr,
                                                  const float* __restrict__ thptr) {
    __shared__ float xiT2[EMBD * 128 * 2];  // [k][i dup pairs] 32 KB
    __shared__ float xjT[EMBD * 64];        // [k][j] 8 KB
    __shared__ float sqi[128], sqj[64];

    const int t  = threadIdx.x;
    const int g  = blockIdx.z;
    const int i0 = blockIdx.y * 128;
    const int j0 = blockIdx.x * 64;
    const int ty = t >> 4, tx = t & 15;
    const int isub = ty * 8, jsub = tx * 4;

    // ---- Early index stores: no data dependence, overlap with everything ----
    {
        const float jbasef = (float)(g * NPG + j0 + jsub);
        const float4 dst4 = make_float4(jbasef, jbasef + 1.f, jbasef + 2.f, jbasef + 3.f);
        const size_t ebase = (size_t)g * ((size_t)NPG * NPG)
                           + (size_t)(i0 + isub) * NPG + (size_t)(j0 + jsub);
#pragma unroll
        for (int r = 0; r < 8; r++) {
            const size_t eidx = ebase + (size_t)r * NPG;
            const float fsrc = (float)(g * NPG + i0 + isub + r);
            st_cs(out + OFF_SRC + eidx, make_float4(fsrc, fsrc, fsrc, fsrc));
            st_cs(out + OFF_DST + eidx, dst4);
        }
    }

    // ---- Stage tiles ----
    const float* base = g_xgT + (size_t)g * (EMBD * NPG);
    for (int e = t; e < 1024; e += 256) {            // i tile: 32k x 128 -> duplicated
        const int k = e >> 5, c = e & 31;
        const float4 v = *(const float4*)(base + k * NPG + i0 + c * 4);
        float4* d = (float4*)&xiT2[k * 256 + c * 8];
        d[0] = make_float4(v.x, v.x, v.y, v.y);
        d[1] = make_float4(v.z, v.z, v.w, v.w);
    }
    for (int e = t; e < 512; e += 256) {             // j tile: 32k x 64
        const int k = e >> 4, c = e & 15;
        ((float4*)xjT)[e] = *(const float4*)(base + k * NPG + j0 + c * 4);
    }
    if (t < 128)        sqi[t]       = g_sq[g * NPG + i0 + t];
    else if (t < 192)   sqj[t - 128] = g_sq[g * NPG + j0 + (t - 128)];
    __syncthreads();

    unsigned long long acc[8][2];
#pragma unroll
    for (int r = 0; r < 8; r++) { acc[r][0] = 0ull; acc[r][1] = 0ull; }

#pragma unroll
    for (int k = 0; k < EMBD; k++) {
        const ulonglong2 b = *(const ulonglong2*)&xjT[k * 64 + jsub];
        const float* ab = &xiT2[k * 256 + isub * 2];
        const ulonglong2 a01 = *(const ulonglong2*)(ab);
        const ulonglong2 a23 = *(const ulonglong2*)(ab + 4);
        const ulonglong2 a45 = *(const ulonglong2*)(ab + 8);
        const ulonglong2 a67 = *(const ulonglong2*)(ab + 12);
        acc[0][0] = ffma2(a01.x, b.x, acc[0][0]); acc[0][1] = ffma2(a01.x, b.y, acc[0][1]);
        acc[1][0] = ffma2(a01.y, b.x, acc[1][0]); acc[1][1] = ffma2(a01.y, b.y, acc[1][1]);
        acc[2][0] = ffma2(a23.x, b.x, acc[2][0]); acc[2][1] = ffma2(a23.x, b.y, acc[2][1]);
        acc[3][0] = ffma2(a23.y, b.x, acc[3][0]); acc[3][1] = ffma2(a23.y, b.y, acc[3][1]);
        acc[4][0] = ffma2(a45.x, b.x, acc[4][0]); acc[4][1] = ffma2(a45.x, b.y, acc[4][1]);
        acc[5][0] = ffma2(a45.y, b.x, acc[5][0]); acc[5][1] = ffma2(a45.y, b.y, acc[5][1]);
        acc[6][0] = ffma2(a67.x, b.x, acc[6][0]); acc[6][1] = ffma2(a67.x, b.y, acc[6][1]);
        acc[7][0] = ffma2(a67.y, b.x, acc[7][0]); acc[7][1] = ffma2(a67.y, b.y, acc[7][1]);
    }

    const float temp = *tptr;
    const float athr = fabsf(*thptr);
    const float sj0 = sqj[jsub], sj1 = sqj[jsub + 1];
    const float sj2 = sqj[jsub + 2], sj3 = sqj[jsub + 3];

#pragma unroll
    for (int r = 0; r < 8; r++) {
        const int il = isub + r;
        const float si = sqi[il];
        float d0, d1, d2, d3;
        unpack2(acc[r][0], d0, d1);
        unpack2(acc[r][1], d2, d3);
        const float D0 = fmaxf(si + sj0 - 2.0f * d0, 0.0f);
        const float D1 = fmaxf(si + sj1 - 2.0f * d1, 0.0f);
        const float D2 = fmaxf(si + sj2 - 2.0f * d2, 0.0f);
        const float D3 = fmaxf(si + sj3 - 2.0f * d3, 0.0f);
        float4 A4;
        A4.x = __fdividef(1.0f, 1.0f + __expf(temp * (D0 - athr)));
        A4.y = __fdividef(1.0f, 1.0f + __expf(temp * (D1 - athr)));
        A4.z = __fdividef(1.0f, 1.0f + __expf(temp * (D2 - athr)));
        A4.w = __fdividef(1.0f, 1.0f + __expf(temp * (D3 - athr)));
        const size_t eidx = (size_t)g * ((size_t)NPG * NPG)
                          + (size_t)(i0 + il) * NPG + (size_t)(j0 + jsub);
        st_cs(out + OFF_EW + eidx, A4);
    }
}

// ---------------------------------------------------------------------------
extern "C" void kernel_launch(void* const* d_in, const int* in_sizes, int n_in,
                              void* d_out, int out_size) {
    const float* x     = (const float*)d_in[0];
    const float* W     = (const float*)d_in[1];
    const float* tptr  = (const float*)d_in[2];
    const float* thptr = (const float*)d_in[3];
    float* out = (float*)d_out;

    k1_gemm<<<NTOT / 32, 256>>>(x, W, out);
    k2_stats<<<1, 1024>>>(out);
    k3_norm<<<NTOT / 256, 256>>>(out);
    k4_pair<<<dim3(16, 8, NG), 256>>>(out, tptr, thptr);
}

// round 5
// speedup vs baseline: 1.1153x; 1.1153x over previous
#include <cuda_runtime.h>
#include <cstdint>

#define NTOT 32768
#define FDIM 128
#define EMBD 32
#define NG   32
#define NPG  1024
#define OFF_SRC 1048576u
#define OFF_DST 34603008u
#define OFF_EW  68157440u

__device__ float g_stats[33];   // [0..31]=centroid, [32]=scale

// ---------------------------------------------------------------------------
__device__ __forceinline__ unsigned long long pack2(float lo, float hi) {
    unsigned long long r;
    asm("mov.b64 %0, {%1, %2};" : "=l"(r) : "f"(lo), "f"(hi));
    return r;
}
__device__ __forceinline__ void unpack2(unsigned long long v, float& lo, float& hi) {
    asm("mov.b64 {%0, %1}, %2;" : "=f"(lo), "=f"(hi) : "l"(v));
}
__device__ __forceinline__ unsigned long long ffma2(unsigned long long a,
                                                    unsigned long long b,
                                                    unsigned long long c) {
    unsigned long long d;
    asm("fma.rn.f32x2 %0, %1, %2, %3;" : "=l"(d) : "l"(a), "l"(b), "l"(c));
    return d;
}
__device__ __forceinline__ void st_cs(float* p, float4 v) {
    asm volatile("st.global.cs.v4.f32 [%0], {%1,%2,%3,%4};"
                 :: "l"(p), "f"(v.x), "f"(v.y), "f"(v.z), "f"(v.w) : "memory");
}

// ---------------------------------------------------------------------------
// K1: xe = x @ W  (32768x128 @ 128x32)
// ---------------------------------------------------------------------------
__global__ __launch_bounds__(256) void k1_gemm(const float* __restrict__ x,
                                               const float* __restrict__ W,
                                               float* __restrict__ xe) {
    __shared__ float ws[FDIM * EMBD];
    __shared__ float xs[32 * FDIM];
    const int t = threadIdx.x;
    const int row0 = blockIdx.x * 32;

    for (int e = t; e < FDIM * EMBD; e += 256) ws[e] = W[e];
    for (int e = t; e < 1024; e += 256)
        ((float4*)xs)[e] = ((const float4*)(x + (size_t)row0 * FDIM))[e];
    __syncthreads();

    const int r  = t >> 3;
    const int d0 = (t & 7) * 4;
    float a0 = 0.f, a1 = 0.f, a2 = 0.f, a3 = 0.f;
#pragma unroll
    for (int k = 0; k < FDIM; k++) {
        const float xv = xs[r * FDIM + k];
        const float4 w4 = *(const float4*)&ws[k * EMBD + d0];
        a0 = fmaf(xv, w4.x, a0);
        a1 = fmaf(xv, w4.y, a1);
        a2 = fmaf(xv, w4.z, a2);
        a3 = fmaf(xv, w4.w, a3);
    }
    *(float4*)&xe[(size_t)(row0 + r) * EMBD + d0] = make_float4(a0, a1, a2, a3);
}

// ---------------------------------------------------------------------------
// K2: centroid + scale from xe[:1024]; rows held in registers.
// ---------------------------------------------------------------------------
__global__ __launch_bounds__(1024) void k2_stats(const float* __restrict__ xe) {
    __shared__ float part[32 * 32];
    __shared__ float cent[EMBD];
    const int t = threadIdx.x;
    const int w = t >> 5, l = t & 31;

    float v[EMBD];
#pragma unroll
    for (int q = 0; q < 8; q++) {
        const float4 f = ((const float4*)(xe + (size_t)t * EMBD))[q];
        v[4 * q] = f.x; v[4 * q + 1] = f.y; v[4 * q + 2] = f.z; v[4 * q + 3] = f.w;
    }
#pragma unroll
    for (int d = 0; d < EMBD; d++) {
        float s = v[d];
#pragma unroll
        for (int o = 16; o; o >>= 1) s += __shfl_xor_sync(0xffffffffu, s, o);
        if (l == 0) part[w * 32 + d] = s;
    }
    __syncthreads();
    if (w == 0) {
        float s = 0.f;
#pragma unroll
        for (int b = 0; b < 32; b++) s += part[b * 32 + l];
        const float c = s * (1.0f / 1024.0f);
        cent[l] = c;
        g_stats[l] = c;
    }
    __syncthreads();
#pragma unroll
    for (int d = 0; d < EMBD; d++) {
        float m = fabsf(v[d] - cent[d]);
#pragma unroll
        for (int o = 16; o; o >>= 1) m = fmaxf(m, __shfl_xor_sync(0xffffffffu, m, o));
        if (l == 0) part[w * 32 + d] = m;
    }
    __syncthreads();
    if (w == 0) {
        float m = 0.f;
#pragma unroll
        for (int b = 0; b < 32; b++) m = fmaxf(m, part[b * 32 + l]);
#pragma unroll
        for (int o = 16; o; o >>= 1) m = fmaxf(m, __shfl_xor_sync(0xffffffffu, m, o));
        if (l == 0) g_stats[32] = 0.9f / m;
    }
}

// ---------------------------------------------------------------------------
// K4: fused normalize + pairwise. 128x64 tiles, 256 threads, 8x4/thread.
//  - Tiles staged directly from xe with (v-cent)*scale applied; row norms
//    computed during staging (k3 eliminated).
//  - R2-proven mainloop (2x LDS.128 A + 1x LDS.128 B + pack movs + 16 FFMA2).
//  - src/dst index stores PACED: one float4 .cs store per k-step inside the
//    mainloop (16 total) so 268MB of index traffic drains under the FMAs.
// ---------------------------------------------------------------------------
__global__ __launch_bounds__(256, 4) void k4_pair(const float* __restrict__ xe,
                                                  float* __restrict__ out,
                                                  const float* __restrict__ tptr,
                                                  const float* __restrict__ thptr) {
    __shared__ float xiT[EMBD * 128];   // [k][i] 16 KB
    __shared__ float xjT[EMBD * 64];    // [k][j] 8 KB
    __shared__ float psqi[256];
    __shared__ float psqj[128];
    __shared__ float sqi[128], sqj[64];

    const int t  = threadIdx.x;
    const int g  = blockIdx.z;
    const int i0 = blockIdx.y * 128;
    const int j0 = blockIdx.x * 64;
    const int ty = t >> 4, tx = t & 15;
    const int isub = ty * 8, jsub = tx * 4;

    const float scale = g_stats[32];

    // ---- Stage i-tile: thread t -> row r=t>>1, dim-half h=t&1 ----
    {
        const int r = t >> 1, h = t & 1;
        const float* xrow = xe + (size_t)(g * NPG + i0 + r) * EMBD + h * 16;
        float ps = 0.f;
#pragma unroll
        for (int q = 0; q < 4; q++) {
            const float4 v = ((const float4*)xrow)[q];
            const int k = h * 16 + q * 4;
            const float a0 = (v.x - g_stats[k + 0]) * scale;
            const float a1 = (v.y - g_stats[k + 1]) * scale;
            const float a2 = (v.z - g_stats[k + 2]) * scale;
            const float a3 = (v.w - g_stats[k + 3]) * scale;
            xiT[(k + 0) * 128 + r] = a0;
            xiT[(k + 1) * 128 + r] = a1;
            xiT[(k + 2) * 128 + r] = a2;
            xiT[(k + 3) * 128 + r] = a3;
            ps += a0 * a0 + a1 * a1 + a2 * a2 + a3 * a3;
        }
        psqi[t] = ps;
    }
    // ---- Stage j-tile: threads 0..127 -> row r=t>>1, half h=t&1 ----
    if (t < 128) {
        const int r = t >> 1, h = t & 1;
        const float* xrow = xe + (size_t)(g * NPG + j0 + r) * EMBD + h * 16;
        float ps = 0.f;
#pragma unroll
        for (int q = 0; q < 4; q++) {
            const float4 v = ((const float4*)xrow)[q];
            const int k = h * 16 + q * 4;
            const float a0 = (v.x - g_stats[k + 0]) * scale;
            const float a1 = (v.y - g_stats[k + 1]) * scale;
            const float a2 = (v.z - g_stats[k + 2]) * scale;
            const float a3 = (v.w - g_stats[k + 3]) * scale;
            xjT[(k + 0) * 64 + r] = a0;
            xjT[(k + 1) * 64 + r] = a1;
            xjT[(k + 2) * 64 + r] = a2;
            xjT[(k + 3) * 64 + r] = a3;
            ps += a0 * a0 + a1 * a1 + a2 * a2 + a3 * a3;
        }
        psqj[t] = ps;
    }
    __syncthreads();
    if (t < 128)        sqi[t]       = psqi[2 * t] + psqi[2 * t + 1];
    else if (t < 192)   sqj[t - 128] = psqj[2 * (t - 128)] + psqj[2 * (t - 128) + 1];
    __syncthreads();

    // ---- Mainloop with paced index stores ----
    const size_t ebase = (size_t)g * ((size_t)NPG * NPG)
                       + (size_t)(i0 + isub) * NPG + (size_t)(j0 + jsub);
    float* const pSrc = out + OFF_SRC + ebase;
    float* const pDst = out + OFF_DST + ebase;
    const float fsrc0 = (float)(g * NPG + i0 + isub);
    const float jbasef = (float)(g * NPG + j0 + jsub);
    const float4 dst4 = make_float4(jbasef, jbasef + 1.f, jbasef + 2.f, jbasef + 3.f);

    unsigned long long acc[8][2];
#pragma unroll
    for (int r = 0; r < 8; r++) { acc[r][0] = 0ull; acc[r][1] = 0ull; }

#pragma unroll
    for (int k = 0; k < EMBD; k++) {
        const float4 A0 = *(const float4*)&xiT[k * 128 + isub];
        const float4 A1 = *(const float4*)&xiT[k * 128 + isub + 4];
        const float4 B  = *(const float4*)&xjT[k * 64 + jsub];
        const unsigned long long bp0 = pack2(B.x, B.y);
        const unsigned long long bp1 = pack2(B.z, B.w);
        const float av[8] = {A0.x, A0.y, A0.z, A0.w, A1.x, A1.y, A1.z, A1.w};
#pragma unroll
        for (int r = 0; r < 8; r++) {
            const unsigned long long as = pack2(av[r], av[r]);
            acc[r][0] = ffma2(as, bp0, acc[r][0]);
            acc[r][1] = ffma2(as, bp1, acc[r][1]);
        }
        // paced, data-independent index stores: one float4 per k-step
        if (k < 8) {
            const float f = fsrc0 + (float)k;
            st_cs(pSrc + (size_t)k * NPG, make_float4(f, f, f, f));
        } else if (k < 16) {
            st_cs(pDst + (size_t)(k - 8) * NPG, dst4);
        }
    }

    // ---- Epilogue: D -> sigmoid -> edge_weight ----
    const float temp = *tptr;
    const float athr = fabsf(*thptr);
    const float sj0 = sqj[jsub], sj1 = sqj[jsub + 1];
    const float sj2 = sqj[jsub + 2], sj3 = sqj[jsub + 3];

#pragma unroll
    for (int r = 0; r < 8; r++) {
        const float si = sqi[isub + r];
        float d0, d1, d2, d3;
        unpack2(acc[r][0], d0, d1);
        unpack2(acc[r][1], d2, d3);
        const float D0 = fmaxf(si + sj0 - 2.0f * d0, 0.0f);
        const float D1 = fmaxf(si + sj1 - 2.0f * d1, 0.0f);
        const float D2 = fmaxf(si + sj2 - 2.0f * d2, 0.0f);
        const float D3 = fmaxf(si + sj3 - 2.0f * d3, 0.0f);
        float4 A4;
        A4.x = __fdividef(1.0f, 1.0f + __expf(temp * (D0 - athr)));
        A4.y = __fdividef(1.0f, 1.0f + __expf(temp * (D1 - athr)));
        A4.z = __fdividef(1.0f, 1.0f + __expf(temp * (D2 - athr)));
        A4.w = __fdividef(1.0f, 1.0f + __expf(temp * (D3 - athr)));
        st_cs(out + OFF_EW + ebase + (size_t)r * NPG, A4);
    }
}

// ---------------------------------------------------------------------------
extern "C" void kernel_launch(void* const* d_in, const int* in_sizes, int n_in,
                              void* d_out, int out_size) {
    const float* x     = (const float*)d_in[0];
    const float* W     = (const float*)d_in[1];
    const float* tptr  = (const float*)d_in[2];
    const float* thptr = (const float*)d_in[3];
    float* out = (float*)d_out;

    k1_gemm<<<NTOT / 32, 256>>>(x, W, out);
    k2_stats<<<1, 1024>>>(out);
    k4_pair<<<dim3(16, 8, NG), 256>>>(out, out, tptr, thptr);
}

// round 8
// speedup vs baseline: 1.3366x; 1.1985x over previous
#include <cuda_runtime.h>
#include <cstdint>

#define NTOT 32768
#define FDIM 128
#define EMBD 32
#define NG   32
#define NPG  1024
#define OFF_SRC 1048576u
#define OFF_DST 34603008u
#define OFF_EW  68157440u

__device__ float g_xgT[NG * EMBD * NPG];   // [g][k][i]
__device__ float g_sq[NTOT];
__device__ float g_stats[33];              // [0..31]=centroid, [32]=scale

// ---------------------------------------------------------------------------
__device__ __forceinline__ unsigned long long pack2(float lo, float hi) {
    unsigned long long r;
    asm("mov.b64 %0, {%1, %2};" : "=l"(r) : "f"(lo), "f"(hi));
    return r;
}
__device__ __forceinline__ void unpack2(unsigned long long v, float& lo, float& hi) {
    asm("mov.b64 {%0, %1}, %2;" : "=f"(lo), "=f"(hi) : "l"(v));
}
__device__ __forceinline__ unsigned long long ffma2(unsigned long long a,
                                                    unsigned long long b,
                                                    unsigned long long c) {
    unsigned long long d;
    asm("fma.rn.f32x2 %0, %1, %2, %3;" : "=l"(d) : "l"(a), "l"(b), "l"(c));
    return d;
}
__device__ __forceinline__ void st_cs(float* p, float4 v) {
    asm volatile("st.global.cs.v4.f32 [%0], {%1,%2,%3,%4};"
                 :: "l"(p), "f"(v.x), "f"(v.y), "f"(v.z), "f"(v.w) : "memory");
}

// ---------------------------------------------------------------------------
// K1 v3: xe = x @ W. 128 rows/block, k in 4 chunks of 32.
//  - xsh padded to stride 36 -> scalar x LDS conflict-free.
//  - W staged [k][d]: ulonglong2 load = two ready-packed f32x2 operand pairs.
//  - 4 rows x 4 dims per thread, 8 FFMA2 per k-step. 26.5 KB smem.
// ---------------------------------------------------------------------------
__global__ __launch_bounds__(256) void k1_gemm(const float* __restrict__ x,
                                               const float* __restrict__ W,
                                               float* __restrict__ xe) {
    __shared__ float xsh[128 * 36];    // [r][k'] 18.4 KB
    __shared__ float wsh[2][32 * 32];  // [buf][k'][d] 8 KB
    const int t = threadIdx.x;
    const int row0 = blockIdx.x * 128;
    const int tx = t & 7;              // dim group (4 dims)
    const int ty = t >> 3;             // row base 0..31 (rows ty + 32*i)

    unsigned long long acc[4][2];
#pragma unroll
    for (int i = 0; i < 4; i++) { acc[i][0] = 0ull; acc[i][1] = 0ull; }

#pragma unroll
    for (int h = 0; h < 4; h++) {
        __syncthreads();
        for (int e = t; e < 1024; e += 256) {           // x chunk: 128 rows x 8 float4
            const int r = e >> 3, c = e & 7;
            *(float4*)&xsh[r * 36 + c * 4] =
                *(const float4*)(x + (size_t)(row0 + r) * FDIM + h * 32 + c * 4);
        }
        for (int e = t; e < 256; e += 256) {            // W chunk: 32 k x 8 float4
            const int k = e >> 3, d = e & 7;
            *(float4*)&wsh[h & 1][k * 32 + d * 4] =
                *(const float4*)(W + (size_t)(h * 32 + k) * EMBD + d * 4);
        }
        __syncthreads();
#pragma unroll 8
        for (int k = 0; k < 32; k++) {
            const ulonglong2 wp = *(const ulonglong2*)&wsh[h & 1][k * 32 + tx * 4];
#pragma unroll
            for (int i = 0; i < 4; i++) {
                const float xv = xsh[(ty + 32 * i) * 36 + k];
                const unsigned long long xd = pack2(xv, xv);
                acc[i][0] = ffma2(xd, wp.x, acc[i][0]);
                acc[i][1] = ffma2(xd, wp.y, acc[i][1]);
            }
        }
    }
#pragma unroll
    for (int i = 0; i < 4; i++) {
        float o0, o1, o2, o3;
        unpack2(acc[i][0], o0, o1);
        unpack2(acc[i][1], o2, o3);
        *(float4*)&xe[(size_t)(row0 + ty + 32 * i) * EMBD + tx * 4] =
            make_float4(o0, o1, o2, o3);
    }
}

// ---------------------------------------------------------------------------
// K2: centroid + scale. 1024 threads, rows held in registers across passes.
// ---------------------------------------------------------------------------
__global__ __launch_bounds__(1024) void k2_stats(const float* __restrict__ xe) {
    __shared__ float part[32 * 32];
    __shared__ float cent[EMBD];
    const int t = threadIdx.x;
    const int w = t >> 5, l = t & 31;

    float v[EMBD];
#pragma unroll
    for (int q = 0; q < 8; q++) {
        const float4 f = ((const float4*)(xe + (size_t)t * EMBD))[q];
        v[4 * q] = f.x; v[4 * q + 1] = f.y; v[4 * q + 2] = f.z; v[4 * q + 3] = f.w;
    }
#pragma unroll
    for (int d = 0; d < EMBD; d++) {
        float s = v[d];
#pragma unroll
        for (int o = 16; o; o >>= 1) s += __shfl_xor_sync(0xffffffffu, s, o);
        if (l == 0) part[w * 32 + d] = s;
    }
    __syncthreads();
    if (w == 0) {
        float s = 0.f;
#pragma unroll
        for (int b = 0; b < 32; b++) s += part[b * 32 + l];
        const float c = s * (1.0f / 1024.0f);
        cent[l] = c;
        g_stats[l] = c;
    }
    __syncthreads();
#pragma unroll
    for (int d = 0; d < EMBD; d++) {
        float m = fabsf(v[d] - cent[d]);
#pragma unroll
        for (int o = 16; o; o >>= 1) m = fmaxf(m, __shfl_xor_sync(0xffffffffu, m, o));
        if (l == 0) part[w * 32 + d] = m;
    }
    __syncthreads();
    if (w == 0) {
        float m = 0.f;
#pragma unroll
        for (int b = 0; b < 32; b++) m = fmaxf(m, part[b * 32 + l]);
#pragma unroll
        for (int o = 16; o; o >>= 1) m = fmaxf(m, __shfl_xor_sync(0xffffffffu, m, o));
        if (l == 0) g_stats[32] = 0.9f / m;
    }
}

// ---------------------------------------------------------------------------
// K3: normalize -> transposed per-graph layout + row norms
// ---------------------------------------------------------------------------
__global__ __launch_bounds__(256) void k3_norm(const float* __restrict__ xe) {
    const int i = blockIdx.x * 256 + threadIdx.x;
    const float scale = g_stats[32];
    const int g  = i >> 10;
    const int il = i & 1023;
    const float* row = xe + (size_t)i * EMBD;
    float* dstb = g_xgT + (size_t)g * (EMBD * NPG) + il;
    float s = 0.f;
#pragma unroll
    for (int k = 0; k < EMBD; k++) {
        const float v = (row[k] - g_stats[k]) * scale;
        dstb[k * NPG] = v;
        s = fmaf(v, v, s);
    }
    g_sq[i] = s;
}

// ---------------------------------------------------------------------------
// K4: EXACT R2 version (proven 81.4us). 128x64 tiles, 256 threads, 8x4/thread,
// f32x2 FMA, 4 blocks/SM, streaming .cs stores in epilogue.
// ---------------------------------------------------------------------------
__global__ __launch_bounds__(256, 4) void k4_pair(float* __restrict__ out,
                                                  const float* __restrict__ tptr,
                                                  const float* __restrict__ thptr) {
    __shared__ float xiT[EMBD * 128];   // [k][i] 16 KB
    __shared__ float xjT[EMBD * 64];    // [k][j] 8 KB
    __shared__ float sqi[128], sqj[64];

    const int t  = threadIdx.x;
    const int g  = blockIdx.z;
    const int i0 = blockIdx.y * 128;
    const int j0 = blockIdx.x * 64;
    const float* base = g_xgT + (size_t)g * (EMBD * NPG);

    for (int e = t; e < 1024; e += 256) {
        const int k = e >> 5, c = e & 31;
        ((float4*)xiT)[e] = *(const float4*)(base + k * NPG + i0 + c * 4);
    }
    for (int e = t; e < 512; e += 256) {
        const int k = e >> 4, c = e & 15;
        ((float4*)xjT)[e] = *(const float4*)(base + k * NPG + j0 + c * 4);
    }
    if (t < 128)        sqi[t]       = g_sq[g * NPG + i0 + t];
    else if (t < 192)   sqj[t - 128] = g_sq[g * NPG + j0 + (t - 128)];
    __syncthreads();

    const int ty = t >> 4, tx = t & 15;
    const int isub = ty * 8, jsub = tx * 4;

    unsigned long long acc[8][2];
#pragma unroll
    for (int r = 0; r < 8; r++) { acc[r][0] = 0ull; acc[r][1] = 0ull; }

#pragma unroll
    for (int k = 0; k < EMBD; k++) {
        const float4 A0 = *(const float4*)&xiT[k * 128 + isub];
        const float4 A1 = *(const float4*)&xiT[k * 128 + isub + 4];
        const float4 B  = *(const float4*)&xjT[k * 64 + jsub];
        const unsigned long long bp0 = pack2(B.x, B.y);
        const unsigned long long bp1 = pack2(B.z, B.w);
        const float av[8] = {A0.x, A0.y, A0.z, A0.w, A1.x, A1.y, A1.z, A1.w};
#pragma unroll
        for (int r = 0; r < 8; r++) {
            const unsigned long long as = pack2(av[r], av[r]);
            acc[r][0] = ffma2(as, bp0, acc[r][0]);
            acc[r][1] = ffma2(as, bp1, acc[r][1]);
        }
    }

    const float temp = *tptr;
    const float athr = fabsf(*thptr);
    const float sj0 = sqj[jsub], sj1 = sqj[jsub + 1];
    const float sj2 = sqj[jsub + 2], sj3 = sqj[jsub + 3];
    const float jbasef = (float)(g * NPG + j0 + jsub);
    const float4 dst4 = make_float4(jbasef, jbasef + 1.f, jbasef + 2.f, jbasef + 3.f);

#pragma unroll
    for (int r = 0; r < 8; r++) {
        const int il = isub + r;
        const float si = sqi[il];
        float d0, d1, d2, d3;
        unpack2(acc[r][0], d0, d1);
        unpack2(acc[r][1], d2, d3);
        const float D0 = fmaxf(si + sj0 - 2.0f * d0, 0.0f);
        const float D1 = fmaxf(si + sj1 - 2.0f * d1, 0.0f);
        const float D2 = fmaxf(si + sj2 - 2.0f * d2, 0.0f);
        const float D3 = fmaxf(si + sj3 - 2.0f * d3, 0.0f);
        float4 A4;
        A4.x = __fdividef(1.0f, 1.0f + __expf(temp * (D0 - athr)));
        A4.y = __fdividef(1.0f, 1.0f + __expf(temp * (D1 - athr)));
        A4.z = __fdividef(1.0f, 1.0f + __expf(temp * (D2 - athr)));
        A4.w = __fdividef(1.0f, 1.0f + __expf(temp * (D3 - athr)));

        const size_t eidx = (size_t)g * ((size_t)NPG * NPG)
                          + (size_t)(i0 + il) * NPG + (size_t)(j0 + jsub);
        st_cs(out + OFF_EW + eidx, A4);
        const float fsrc = (float)(g * NPG + i0 + il);
        st_cs(out + OFF_SRC + eidx, make_float4(fsrc, fsrc, fsrc, fsrc));
        st_cs(out + OFF_DST + eidx, dst4);
    }
}

// ---------------------------------------------------------------------------
extern "C" void kernel_launch(void* const* d_in, const int* in_sizes, int n_in,
                              void* d_out, int out_size) {
    const float* x     = (const float*)d_in[0];
    const float* W     = (const float*)d_in[1];
    const float* tptr  = (const float*)d_in[2];
    const float* thptr = (const float*)d_in[3];
    float* out = (float*)d_out;

    k1_gemm<<<NTOT / 128, 256>>>(x, W, out);
    k2_stats<<<1, 1024>>>(out);
    k3_norm<<<NTOT / 256, 256>>>(out);
    k4_pair<<<dim3(16, 8, NG), 256>>>(out, tptr, thptr);
}